// round 10
// baseline (speedup 1.0000x reference)
#include <cuda_runtime.h>
#include <cuda_bf16.h>
#include <math.h>

// Problem constants: B=32, S=512, V=32000, D=512, H=256, L=9, 4H=1024, 2H=512

// ------------------------- static device scratch -------------------------
__device__ float g_x0[512 * 32 * 512];        // embeddings  [t][b][d]
__device__ float g_x1[512 * 32 * 512];        // layer-0 out [t][b][2H]
__device__ float g_x2[512 * 32 * 512];        // layer-1 out [t][b][2H]
__device__ float g_preF[512 * 32 * 1024];     // x@Wih^T + biases, fwd
__device__ float g_preB[512 * 32 * 1024];     // bwd
__device__ float g_h[2][2][256 * 32];         // [dir][parity][j*32+b]
__device__ unsigned g_bar[2];                 // per-direction step barrier
__device__ float g_crf[32];                   // per-batch (logZ - gold)

__device__ __forceinline__ float tf32r(float x) {
    float y;
    asm("cvt.rna.tf32.f32 %0, %1;" : "=f"(y) : "f"(x));
    return y;
}

__device__ __forceinline__ unsigned ld_acq_u32(const unsigned* p) {
    unsigned v;
    asm volatile("ld.acquire.gpu.global.u32 %0, [%1];" : "=r"(v) : "l"(p));
    return v;
}
__device__ __forceinline__ void red_rel_add(unsigned* p, unsigned v) {
    asm volatile("red.release.gpu.global.add.u32 [%0], %1;" :: "l"(p), "r"(v) : "memory");
}

// ------------------------- embedding gather -------------------------
__global__ __launch_bounds__(256) void embed_k(const int* __restrict__ ids,
                                               const int* __restrict__ msk,
                                               const float* __restrict__ emb) {
    int f = blockIdx.x * 256 + threadIdx.x;   // float4 index, 2,097,152 total
    int m = f >> 7;                            // row = t*32+b (128 float4/row)
    int d4 = f & 127;
    int b = m & 31, t = m >> 5;
    float mm = (float)msk[b * 512 + t];
    int id = ids[b * 512 + t];
    float4 v = __ldg((const float4*)emb + (size_t)id * 128 + d4);
    v.x *= mm; v.y *= mm; v.z *= mm; v.w *= mm;
    ((float4*)g_x0)[f] = v;
}

// ------------------------- reset barrier + h buffers -------------------------
__global__ void reset_k() {
    int i = blockIdx.x * blockDim.x + threadIdx.x;
    if (i < 2 * 2 * 256 * 32) ((float*)g_h)[i] = 0.0f;
    if (i < 2) g_bar[i] = 0u;
}

// ------------------------- pre-activation SGEMM (TF32-emulated inputs) -----
// C[m][n] = sum_k tf32(A[m][k]) * tf32(W[n][k]) + bih[n] + bhh[n]
// M=16384, N=1024, K=512.  BM=BN=128, BK=16, 256 threads, 8x8 micro-tile.
__global__ __launch_bounds__(256) void gemm_pre(const float* __restrict__ wih,
                                                const float* __restrict__ bih,
                                                const float* __restrict__ bhh,
                                                int layer) {
    __shared__ float As[16 * 128];
    __shared__ float Bs[16 * 128];
    const float* A = layer ? g_x1 : g_x0;
    int dir = blockIdx.z;
    const float* Wp = wih + (size_t)(layer * 2 + dir) * 1024 * 512;
    const float* bi = bih + (layer * 2 + dir) * 1024;
    const float* bh = bhh + (layer * 2 + dir) * 1024;
    float* C = dir ? g_preB : g_preF;
    int m0 = blockIdx.x * 128, n0 = blockIdx.y * 128;
    int tid = threadIdx.x;
    int tx = tid & 15, ty = tid >> 4;

    float acc[8][8];
#pragma unroll
    for (int i = 0; i < 8; ++i)
#pragma unroll
        for (int j = 0; j < 8; ++j) acc[i][j] = 0.0f;

    for (int kt = 0; kt < 32; ++kt) {
        int k0 = kt * 16;
        float4 aR[2], bR[2];
#pragma unroll
        for (int i = 0; i < 2; ++i) {
            int u = tid * 2 + i;
            int row = u >> 2, kq = u & 3;
            aR[i] = __ldg((const float4*)(A + (size_t)(m0 + row) * 512 + k0 + kq * 4));
            bR[i] = __ldg((const float4*)(Wp + (size_t)(n0 + row) * 512 + k0 + kq * 4));
        }
        __syncthreads();   // previous compute done before overwriting tiles
#pragma unroll
        for (int i = 0; i < 2; ++i) {
            int u = tid * 2 + i;
            int row = u >> 2, kq = u & 3;
            As[(kq * 4 + 0) * 128 + row] = tf32r(aR[i].x);
            As[(kq * 4 + 1) * 128 + row] = tf32r(aR[i].y);
            As[(kq * 4 + 2) * 128 + row] = tf32r(aR[i].z);
            As[(kq * 4 + 3) * 128 + row] = tf32r(aR[i].w);
            Bs[(kq * 4 + 0) * 128 + row] = tf32r(bR[i].x);
            Bs[(kq * 4 + 1) * 128 + row] = tf32r(bR[i].y);
            Bs[(kq * 4 + 2) * 128 + row] = tf32r(bR[i].z);
            Bs[(kq * 4 + 3) * 128 + row] = tf32r(bR[i].w);
        }
        __syncthreads();
#pragma unroll
        for (int k = 0; k < 16; ++k) {
            float4 a0 = *(const float4*)&As[k * 128 + ty * 8];
            float4 a1 = *(const float4*)&As[k * 128 + ty * 8 + 4];
            float4 b0 = *(const float4*)&Bs[k * 128 + tx * 8];
            float4 b1 = *(const float4*)&Bs[k * 128 + tx * 8 + 4];
            float av[8] = {a0.x, a0.y, a0.z, a0.w, a1.x, a1.y, a1.z, a1.w};
            float bv[8] = {b0.x, b0.y, b0.z, b0.w, b1.x, b1.y, b1.z, b1.w};
#pragma unroll
            for (int i = 0; i < 8; ++i)
#pragma unroll
                for (int j = 0; j < 8; ++j) acc[i][j] += av[i] * bv[j];
        }
    }
    int col = n0 + tx * 8;
    float bb[8];
#pragma unroll
    for (int j = 0; j < 8; ++j) bb[j] = bi[col + j] + bh[col + j];
#pragma unroll
    for (int i = 0; i < 8; ++i) {
        int m = m0 + ty * 8 + i;
        float4 o0, o1;
        o0.x = acc[i][0] + bb[0]; o0.y = acc[i][1] + bb[1];
        o0.z = acc[i][2] + bb[2]; o0.w = acc[i][3] + bb[3];
        o1.x = acc[i][4] + bb[4]; o1.y = acc[i][5] + bb[5];
        o1.z = acc[i][6] + bb[6]; o1.w = acc[i][7] + bb[7];
        *(float4*)(C + (size_t)m * 1024 + col) = o0;
        *(float4*)(C + (size_t)m * 1024 + col + 4) = o1;
    }
}

// ------------------------- persistent BiLSTM recurrence -------------------------
// 128 CTAs: CTAs 0..63 = fwd, 64..127 = bwd. Each CTA owns 4 hidden units.
// 128 threads: (rg = tid>>5 in 0..3, b = tid&31).
//   dot phase:  thread computes gate rg for units 0..3, batch b (full K=256).
//   act phase:  thread owns unit rg, batch b; c kept in a register all 512 steps.
// h@Whh^T inputs TF32-rounded (Whh once at load, h at the smem copy).
__global__ __launch_bounds__(128, 1) void lstm_k(const float* __restrict__ whh,
                                                 int layer) {
    __shared__ float wsm[16 * 256];   // Whh slice, [gate*4+unit][k], tf32-rounded
    __shared__ float hsm[8192];       // h_prev (tf32), [k][b]; head reused as gate xchg
    const int tid = threadIdx.x;
    const int cta = blockIdx.x;
    const int dir = cta >> 6;
    const int s = cta & 63;           // units s*4 .. s*4+3
    const int rg = tid >> 5;
    const int b = tid & 31;
    const float* W = whh + (size_t)(layer * 2 + dir) * 1024 * 256;
    const float* pre = dir ? g_preB : g_preF;
    float* xout = layer ? g_x2 : g_x1;

    // load Whh slice once (reused for all 512 steps), round to tf32
    {
        float4* w4 = (float4*)wsm;
#pragma unroll
        for (int i = 0; i < 8; ++i) {
            int f = i * 128 + tid;          // 0..1023 float4
            int r16 = f >> 6;               // 0..15
            int kq = f & 63;
            int grow = (r16 >> 2) * 256 + s * 4 + (r16 & 3);
            float4 wv = __ldg((const float4*)(W + (size_t)grow * 256) + kq);
            wv.x = tf32r(wv.x); wv.y = tf32r(wv.y);
            wv.z = tf32r(wv.z); wv.w = tf32r(wv.w);
            w4[f] = wv;
        }
    }
    float c = 0.0f;
    __syncthreads();

    for (int idx = 0; idx < 512; ++idx) {
        const int t = dir ? (511 - idx) : idx;
        if (tid == 0 && idx > 0) {
            unsigned tgt = 64u * (unsigned)idx;
            while (ld_acq_u32(&g_bar[dir]) < tgt) { }
        }
        __syncthreads();   // barrier seen by all; also guards hsm overwrite

        // load previous h into smem (layout [j][b]), tf32-round for the matmul
        {
            const float4* src = (const float4*)g_h[dir][(idx + 1) & 1];
            float4* dst = (float4*)hsm;
#pragma unroll
            for (int i = 0; i < 16; ++i) {
                int f = i * 128 + tid;    // 0..2047 float4
                float4 hv = __ldcg(src + f);
                hv.x = tf32r(hv.x); hv.y = tf32r(hv.y);
                hv.z = tf32r(hv.z); hv.w = tf32r(hv.w);
                dst[f] = hv;
            }
        }
        // issue pre-activation fetch early (gate rg, units 0..3, batch b)
        float4 pv = __ldg((const float4*)(pre + ((size_t)t * 32 + b) * 1024 + rg * 256 + s * 4));
        __syncthreads();

        float a0 = 0.f, a1 = 0.f, a2 = 0.f, a3 = 0.f;
        const float4* w0 = (const float4*)&wsm[(rg * 4 + 0) * 256];
        const float4* w1 = (const float4*)&wsm[(rg * 4 + 1) * 256];
        const float4* w2 = (const float4*)&wsm[(rg * 4 + 2) * 256];
        const float4* w3 = (const float4*)&wsm[(rg * 4 + 3) * 256];
#pragma unroll 8
        for (int k4 = 0; k4 < 64; ++k4) {
            float h0 = hsm[(k4 * 4 + 0) * 32 + b];
            float h1 = hsm[(k4 * 4 + 1) * 32 + b];
            float h2 = hsm[(k4 * 4 + 2) * 32 + b];
            float h3 = hsm[(k4 * 4 + 3) * 32 + b];
            float4 wa = w0[k4], wb = w1[k4], wc = w2[k4], wd = w3[k4];
            a0 += wa.x * h0 + wa.y * h1 + wa.z * h2 + wa.w * h3;
            a1 += wb.x * h0 + wb.y * h1 + wb.z * h2 + wb.w * h3;
            a2 += wc.x * h0 + wc.y * h1 + wc.z * h2 + wc.w * h3;
            a3 += wd.x * h0 + wd.y * h1 + wd.z * h2 + wd.w * h3;
        }
        __syncthreads();          // everyone done reading hsm
        float* gsm = hsm;         // [gate][unit][b] -> g*128 + u*32 + b
        gsm[rg * 128 + 0 * 32 + b] = a0 + pv.x;
        gsm[rg * 128 + 1 * 32 + b] = a1 + pv.y;
        gsm[rg * 128 + 2 * 32 + b] = a2 + pv.z;
        gsm[rg * 128 + 3 * 32 + b] = a3 + pv.w;
        __syncthreads();

        float gi = gsm[0 * 128 + rg * 32 + b];
        float gf = gsm[1 * 128 + rg * 32 + b];
        float gg = gsm[2 * 128 + rg * 32 + b];
        float go = gsm[3 * 128 + rg * 32 + b];
        float si = 1.0f / (1.0f + expf(-gi));
        float sf = 1.0f / (1.0f + expf(-gf));
        float so = 1.0f / (1.0f + expf(-go));
        c = sf * c + si * tanhf(gg);
        float h = so * tanhf(c);
        int j = s * 4 + rg;
        g_h[dir][idx & 1][j * 32 + b] = h;                    // full-precision h
        xout[((size_t)t * 32 + b) * 512 + dir * 256 + j] = h; // full-precision h
        __threadfence();
        __syncthreads();
        if (tid == 0) red_rel_add(&g_bar[dir], 1u);
    }
}

// ------------------------- LayerNorm + classifier (TF32 inputs to matmul) ---
__global__ __launch_bounds__(128) void ln_cls_k(const float* __restrict__ gamma,
                                                const float* __restrict__ beta,
                                                const float* __restrict__ cw,
                                                const float* __restrict__ cb,
                                                float* __restrict__ out) {
    int m = blockIdx.x;               // t*32+b
    int tid = threadIdx.x;
    __shared__ float xs[512];
    __shared__ float rs[8];
    __shared__ float red[9 * 4];
    float4 v = __ldg((const float4*)(g_x2 + (size_t)m * 512) + tid);
    *(float4*)&xs[tid * 4] = v;
    float s = v.x + v.y + v.z + v.w;
    float q = v.x * v.x + v.y * v.y + v.z * v.z + v.w * v.w;
#pragma unroll
    for (int o = 16; o; o >>= 1) {
        s += __shfl_down_sync(0xffffffffu, s, o);
        q += __shfl_down_sync(0xffffffffu, q, o);
    }
    int wid = tid >> 5, lane = tid & 31;
    if (lane == 0) { rs[wid] = s; rs[4 + wid] = q; }
    __syncthreads();
    float S = rs[0] + rs[1] + rs[2] + rs[3];
    float Q = rs[4] + rs[5] + rs[6] + rs[7];
    float mu = S * (1.0f / 512.0f);
    float var = Q * (1.0f / 512.0f) - mu * mu;
    float rstd = rsqrtf(var + 1e-5f);

    int d0 = tid * 4;
    float y0 = (xs[d0 + 0] - mu) * rstd * __ldg(gamma + d0 + 0) + __ldg(beta + d0 + 0);
    float y1 = (xs[d0 + 1] - mu) * rstd * __ldg(gamma + d0 + 1) + __ldg(beta + d0 + 1);
    float y2 = (xs[d0 + 2] - mu) * rstd * __ldg(gamma + d0 + 2) + __ldg(beta + d0 + 2);
    float y3 = (xs[d0 + 3] - mu) * rstd * __ldg(gamma + d0 + 3) + __ldg(beta + d0 + 3);
    float t0 = tf32r(y0), t1 = tf32r(y1), t2 = tf32r(y2), t3 = tf32r(y3);
    float acc[9];
#pragma unroll
    for (int l = 0; l < 9; ++l) {
        const float* w = cw + l * 512 + d0;
        acc[l] = t0 * tf32r(__ldg(w))     + t1 * tf32r(__ldg(w + 1))
               + t2 * tf32r(__ldg(w + 2)) + t3 * tf32r(__ldg(w + 3));
    }
#pragma unroll
    for (int l = 0; l < 9; ++l)
#pragma unroll
        for (int o = 16; o; o >>= 1) acc[l] += __shfl_down_sync(0xffffffffu, acc[l], o);
    if (lane == 0)
#pragma unroll
        for (int l = 0; l < 9; ++l) red[l * 4 + wid] = acc[l];
    __syncthreads();
    if (tid < 9) {
        float r = red[tid * 4] + red[tid * 4 + 1] + red[tid * 4 + 2] + red[tid * 4 + 3]
                + __ldg(cb + tid);
        int b = m & 31, t = m >> 5;
        out[1 + ((size_t)b * 512 + t) * 9 + tid] = r;  // logits (B,S,L)
    }
}

// ------------------------- CRF NLL, one warp per batch -------------------------
__global__ __launch_bounds__(32) void crf_k(const float* __restrict__ out,
                                            const int* __restrict__ labels,
                                            const int* __restrict__ lens,
                                            const float* __restrict__ trans) {
    __shared__ float T[121];          // (L+2)x(L+2) = 11x11
    int b = blockIdx.x;
    int lane = threadIdx.x;
    for (int i = lane; i < 121; i += 32) T[i] = trans[i];
    __syncwarp();
    int len = lens[b];
    const float* lg = out + 1 + (size_t)b * 512 * 9;
    const int* lab = labels + b * 512;

    // forward recursion
    float alpha = (lane < 9) ? T[9 * 11 + lane] + lg[lane] : -1e30f;
    for (int t = 1; t < len; ++t) {
        float e = (lane < 9) ? lg[t * 9 + lane] : 0.0f;
        float vv[9];
        float vmax = -1e30f;
#pragma unroll
        for (int i = 0; i < 9; ++i) {
            float ai = __shfl_sync(0xffffffffu, alpha, i);
            float v = ai + T[i * 11 + (lane < 9 ? lane : 0)];
            vv[i] = v;
            vmax = fmaxf(vmax, v);
        }
        float ssum = 0.0f;
#pragma unroll
        for (int i = 0; i < 9; ++i) ssum += expf(vv[i] - vmax);
        alpha = vmax + logf(ssum) + e;
    }
    // logZ
    float x = (lane < 9) ? alpha + T[lane * 11 + 10] : -1e30f;
    float mx = x;
#pragma unroll
    for (int o = 16; o; o >>= 1) mx = fmaxf(mx, __shfl_xor_sync(0xffffffffu, mx, o));
    float sm = expf(x - mx);
#pragma unroll
    for (int o = 16; o; o >>= 1) sm += __shfl_xor_sync(0xffffffffu, sm, o);
    float logZ = mx + logf(sm);

    // gold score
    float g = 0.0f;
    for (int t = lane; t < len; t += 32) {
        int y = lab[t];
        g += lg[t * 9 + y];
        if (t >= 1) g += T[lab[t - 1] * 11 + y];
    }
#pragma unroll
    for (int o = 16; o; o >>= 1) g += __shfl_xor_sync(0xffffffffu, g, o);
    if (lane == 0) {
        float gold = g + T[9 * 11 + lab[0]] + T[lab[len - 1] * 11 + 10];
        g_crf[b] = logZ - gold;
    }
}

__global__ __launch_bounds__(32) void loss_k(float* __restrict__ out) {
    float v = g_crf[threadIdx.x];
#pragma unroll
    for (int o = 16; o; o >>= 1) v += __shfl_xor_sync(0xffffffffu, v, o);
    if (threadIdx.x == 0) out[0] = v * (1.0f / 32.0f);
}

// ------------------------- launch -------------------------
extern "C" void kernel_launch(void* const* d_in, const int* in_sizes, int n_in,
                              void* d_out, int out_size) {
    const int* ids = (const int*)d_in[0];
    const int* msk = (const int*)d_in[1];
    const int* lens = (const int*)d_in[2];
    const int* labels = (const int*)d_in[3];
    const float* emb = (const float*)d_in[4];
    const float* wih = (const float*)d_in[5];
    const float* whh = (const float*)d_in[6];
    const float* bih = (const float*)d_in[7];
    const float* bhh = (const float*)d_in[8];
    const float* gamma = (const float*)d_in[9];
    const float* beta = (const float*)d_in[10];
    const float* cw = (const float*)d_in[11];
    const float* cb = (const float*)d_in[12];
    const float* trans = (const float*)d_in[13];
    float* out = (float*)d_out;

    embed_k<<<8192, 256>>>(ids, msk, emb);
    for (int l = 0; l < 2; ++l) {
        reset_k<<<128, 256>>>();
        gemm_pre<<<dim3(128, 8, 2), 256>>>(wih, bih, bhh, l);
        lstm_k<<<128, 128>>>(whh, l);
    }
    ln_cls_k<<<16384, 128>>>(gamma, beta, cw, cb, out);
    crf_k<<<32, 32>>>(out, labels, lens, trans);
    loss_k<<<1, 32>>>(out);
}

// round 11
// speedup vs baseline: 1.1733x; 1.1733x over previous
#include <cuda_runtime.h>
#include <cuda_bf16.h>
#include <math.h>

// Problem constants: B=32, S=512, V=32000, D=512, H=256, L=9, 4H=1024, 2H=512

// ------------------------- static device scratch -------------------------
__device__ float g_x0[512 * 32 * 512];        // embeddings  [t][b][d]
__device__ float g_x1[512 * 32 * 512];        // layer-0 out [t][b][2H]
__device__ float g_x2[512 * 32 * 512];        // layer-1 out [t][b][2H]
__device__ float g_preF[512 * 32 * 1024];     // x@Wih^T + biases, fwd
__device__ float g_preB[512 * 32 * 1024];     // bwd
__device__ float g_h[2][2][256 * 32];         // [dir][parity][j*32+b]
__device__ unsigned g_bar[2];                 // per-direction step barrier
__device__ float g_crf[32];                   // per-batch (logZ - gold)

__device__ __forceinline__ float tf32r(float x) {
    float y;
    asm("cvt.rna.tf32.f32 %0, %1;" : "=f"(y) : "f"(x));
    return y;
}

__device__ __forceinline__ unsigned ld_acq_u32(const unsigned* p) {
    unsigned v;
    asm volatile("ld.acquire.gpu.global.u32 %0, [%1];" : "=r"(v) : "l"(p));
    return v;
}
__device__ __forceinline__ void red_rel_add(unsigned* p, unsigned v) {
    asm volatile("red.release.gpu.global.add.u32 [%0], %1;" :: "l"(p), "r"(v) : "memory");
}

// ------------------------- embedding gather -------------------------
__global__ __launch_bounds__(256) void embed_k(const int* __restrict__ ids,
                                               const int* __restrict__ msk,
                                               const float* __restrict__ emb) {
    int f = blockIdx.x * 256 + threadIdx.x;   // float4 index, 2,097,152 total
    int m = f >> 7;                            // row = t*32+b (128 float4/row)
    int d4 = f & 127;
    int b = m & 31, t = m >> 5;
    float mm = (float)msk[b * 512 + t];
    int id = ids[b * 512 + t];
    float4 v = __ldg((const float4*)emb + (size_t)id * 128 + d4);
    v.x *= mm; v.y *= mm; v.z *= mm; v.w *= mm;
    ((float4*)g_x0)[f] = v;
}

// ------------------------- reset barrier + h buffers -------------------------
__global__ void reset_k() {
    int i = blockIdx.x * blockDim.x + threadIdx.x;
    if (i < 2 * 2 * 256 * 32) ((float*)g_h)[i] = 0.0f;
    if (i < 2) g_bar[i] = 0u;
}

// ------------------------- pre-activation GEMM via tf32 mma.sync ----------
// C[m][n] = sum_k tf32(A[m][k]) * tf32(W[n][k]) + bih[n] + bhh[n]
// M=16384, N=1024(per dir), K=512.  BM=BN=128, BK=32, 256 threads.
// Warp grid 4(m) x 2(n); warp tile 32x64; mma.m16n8k8 tf32.
__global__ __launch_bounds__(256, 1) void gemm_pre(const float* __restrict__ wih,
                                                   const float* __restrict__ bih,
                                                   const float* __restrict__ bhh,
                                                   int layer) {
    __shared__ float As[128 * 36];   // [m][k], pad 36 -> fragment LDS conflict-free
    __shared__ float Bs[128 * 36];   // [n][k]
    const float* A = layer ? g_x1 : g_x0;
    int dir = blockIdx.z;
    const float* Wp = wih + (size_t)(layer * 2 + dir) * 1024 * 512;
    const float* bi = bih + (layer * 2 + dir) * 1024;
    const float* bh = bhh + (layer * 2 + dir) * 1024;
    float* C = dir ? g_preB : g_preF;
    int m0 = blockIdx.x * 128, n0 = blockIdx.y * 128;
    int tid = threadIdx.x;
    int wid = tid >> 5, lane = tid & 31;
    int wm = wid & 3, wn = wid >> 2;       // 4x2 warp grid
    int gid = lane >> 2, tg = lane & 3;

    float acc[2][8][4];
#pragma unroll
    for (int mt = 0; mt < 2; ++mt)
#pragma unroll
        for (int nt = 0; nt < 8; ++nt)
#pragma unroll
            for (int i = 0; i < 4; ++i) acc[mt][nt][i] = 0.0f;

    float4 pa[4], pb[4];
#pragma unroll
    for (int i = 0; i < 4; ++i) {       // prefetch k-tile 0
        int f = i * 256 + tid;
        int m = f >> 3, kq = f & 7;
        pa[i] = __ldg((const float4*)(A + (size_t)(m0 + m) * 512 + kq * 4));
        pb[i] = __ldg((const float4*)(Wp + (size_t)(n0 + m) * 512 + kq * 4));
    }

    for (int kt = 0; kt < 16; ++kt) {
        __syncthreads();   // previous compute done before overwriting tiles
#pragma unroll
        for (int i = 0; i < 4; ++i) {
            int f = i * 256 + tid;
            int m = f >> 3, kq = f & 7;
            float4 a = pa[i], b = pb[i];
            a.x = tf32r(a.x); a.y = tf32r(a.y); a.z = tf32r(a.z); a.w = tf32r(a.w);
            b.x = tf32r(b.x); b.y = tf32r(b.y); b.z = tf32r(b.z); b.w = tf32r(b.w);
            *(float4*)&As[m * 36 + kq * 4] = a;
            *(float4*)&Bs[m * 36 + kq * 4] = b;
        }
        __syncthreads();
        if (kt < 15) {
            int k0 = (kt + 1) * 32;
#pragma unroll
            for (int i = 0; i < 4; ++i) {
                int f = i * 256 + tid;
                int m = f >> 3, kq = f & 7;
                pa[i] = __ldg((const float4*)(A + (size_t)(m0 + m) * 512 + k0 + kq * 4));
                pb[i] = __ldg((const float4*)(Wp + (size_t)(n0 + m) * 512 + k0 + kq * 4));
            }
        }
#pragma unroll
        for (int kk = 0; kk < 4; ++kk) {
            int kc = kk * 8;
            unsigned af[2][4];
#pragma unroll
            for (int mt = 0; mt < 2; ++mt) {
                int r = wm * 32 + mt * 16 + gid;
                af[mt][0] = __float_as_uint(As[r * 36 + kc + tg]);
                af[mt][1] = __float_as_uint(As[(r + 8) * 36 + kc + tg]);
                af[mt][2] = __float_as_uint(As[r * 36 + kc + tg + 4]);
                af[mt][3] = __float_as_uint(As[(r + 8) * 36 + kc + tg + 4]);
            }
#pragma unroll
            for (int nt = 0; nt < 8; ++nt) {
                int n = wn * 64 + nt * 8 + gid;
                unsigned b0 = __float_as_uint(Bs[n * 36 + kc + tg]);
                unsigned b1 = __float_as_uint(Bs[n * 36 + kc + tg + 4]);
#pragma unroll
                for (int mt = 0; mt < 2; ++mt) {
                    asm volatile(
                        "mma.sync.aligned.m16n8k8.row.col.f32.tf32.tf32.f32 "
                        "{%0,%1,%2,%3}, {%4,%5,%6,%7}, {%8,%9}, {%0,%1,%2,%3};"
                        : "+f"(acc[mt][nt][0]), "+f"(acc[mt][nt][1]),
                          "+f"(acc[mt][nt][2]), "+f"(acc[mt][nt][3])
                        : "r"(af[mt][0]), "r"(af[mt][1]), "r"(af[mt][2]), "r"(af[mt][3]),
                          "r"(b0), "r"(b1));
                }
            }
        }
    }
    // epilogue: add biases, store float2s
#pragma unroll
    for (int nt = 0; nt < 8; ++nt) {
        int colb = n0 + wn * 64 + nt * 8 + tg * 2;
        float bb0 = __ldg(bi + colb) + __ldg(bh + colb);
        float bb1 = __ldg(bi + colb + 1) + __ldg(bh + colb + 1);
#pragma unroll
        for (int mt = 0; mt < 2; ++mt) {
            int r0 = m0 + wm * 32 + mt * 16 + gid;
            float2 v0, v1;
            v0.x = acc[mt][nt][0] + bb0; v0.y = acc[mt][nt][1] + bb1;
            v1.x = acc[mt][nt][2] + bb0; v1.y = acc[mt][nt][3] + bb1;
            *(float2*)(C + (size_t)r0 * 1024 + colb) = v0;
            *(float2*)(C + (size_t)(r0 + 8) * 1024 + colb) = v1;
        }
    }
}

// ------------------------- persistent BiLSTM recurrence -------------------------
// 128 CTAs: CTAs 0..63 = fwd, 64..127 = bwd. Each CTA owns 4 hidden units.
// 128 threads: (rg = tid>>5 in 0..3, b = tid&31).
__global__ __launch_bounds__(128, 1) void lstm_k(const float* __restrict__ whh,
                                                 int layer) {
    __shared__ float wsm[16 * 256];   // Whh slice, [gate*4+unit][k], tf32-rounded
    __shared__ float hsm[8192];       // h_prev (tf32), [k][b]; head reused as gate xchg
    const int tid = threadIdx.x;
    const int cta = blockIdx.x;
    const int dir = cta >> 6;
    const int s = cta & 63;           // units s*4 .. s*4+3
    const int rg = tid >> 5;
    const int b = tid & 31;
    const float* W = whh + (size_t)(layer * 2 + dir) * 1024 * 256;
    const float* pre = dir ? g_preB : g_preF;
    float* xout = layer ? g_x2 : g_x1;

    // load Whh slice once (reused for all 512 steps), round to tf32
    {
        float4* w4 = (float4*)wsm;
#pragma unroll
        for (int i = 0; i < 8; ++i) {
            int f = i * 128 + tid;          // 0..1023 float4
            int r16 = f >> 6;               // 0..15
            int kq = f & 63;
            int grow = (r16 >> 2) * 256 + s * 4 + (r16 & 3);
            float4 wv = __ldg((const float4*)(W + (size_t)grow * 256) + kq);
            wv.x = tf32r(wv.x); wv.y = tf32r(wv.y);
            wv.z = tf32r(wv.z); wv.w = tf32r(wv.w);
            w4[f] = wv;
        }
    }
    float c = 0.0f;
    __syncthreads();

    for (int idx = 0; idx < 512; ++idx) {
        const int t = dir ? (511 - idx) : idx;
        if (tid == 0 && idx > 0) {
            unsigned tgt = 64u * (unsigned)idx;
            while (ld_acq_u32(&g_bar[dir]) < tgt) { }
        }
        __syncthreads();   // barrier seen by all; also guards hsm overwrite

        // load previous h into smem (layout [j][b]), tf32-round for the matmul
        {
            const float4* src = (const float4*)g_h[dir][(idx + 1) & 1];
            float4* dst = (float4*)hsm;
#pragma unroll
            for (int i = 0; i < 16; ++i) {
                int f = i * 128 + tid;    // 0..2047 float4
                float4 hv = __ldcg(src + f);
                hv.x = tf32r(hv.x); hv.y = tf32r(hv.y);
                hv.z = tf32r(hv.z); hv.w = tf32r(hv.w);
                dst[f] = hv;
            }
        }
        // issue pre-activation fetch early (gate rg, units 0..3, batch b)
        float4 pv = __ldg((const float4*)(pre + ((size_t)t * 32 + b) * 1024 + rg * 256 + s * 4));
        __syncthreads();

        float a0 = 0.f, a1 = 0.f, a2 = 0.f, a3 = 0.f;
        const float4* w0 = (const float4*)&wsm[(rg * 4 + 0) * 256];
        const float4* w1 = (const float4*)&wsm[(rg * 4 + 1) * 256];
        const float4* w2 = (const float4*)&wsm[(rg * 4 + 2) * 256];
        const float4* w3 = (const float4*)&wsm[(rg * 4 + 3) * 256];
#pragma unroll 8
        for (int k4 = 0; k4 < 64; ++k4) {
            float h0 = hsm[(k4 * 4 + 0) * 32 + b];
            float h1 = hsm[(k4 * 4 + 1) * 32 + b];
            float h2 = hsm[(k4 * 4 + 2) * 32 + b];
            float h3 = hsm[(k4 * 4 + 3) * 32 + b];
            float4 wa = w0[k4], wb = w1[k4], wc = w2[k4], wd = w3[k4];
            a0 += wa.x * h0 + wa.y * h1 + wa.z * h2 + wa.w * h3;
            a1 += wb.x * h0 + wb.y * h1 + wb.z * h2 + wb.w * h3;
            a2 += wc.x * h0 + wc.y * h1 + wc.z * h2 + wc.w * h3;
            a3 += wd.x * h0 + wd.y * h1 + wd.z * h2 + wd.w * h3;
        }
        __syncthreads();          // everyone done reading hsm
        float* gsm = hsm;         // [gate][unit][b] -> g*128 + u*32 + b
        gsm[rg * 128 + 0 * 32 + b] = a0 + pv.x;
        gsm[rg * 128 + 1 * 32 + b] = a1 + pv.y;
        gsm[rg * 128 + 2 * 32 + b] = a2 + pv.z;
        gsm[rg * 128 + 3 * 32 + b] = a3 + pv.w;
        __syncthreads();

        float gi = gsm[0 * 128 + rg * 32 + b];
        float gf = gsm[1 * 128 + rg * 32 + b];
        float gg = gsm[2 * 128 + rg * 32 + b];
        float go = gsm[3 * 128 + rg * 32 + b];
        float si = 1.0f / (1.0f + expf(-gi));
        float sf = 1.0f / (1.0f + expf(-gf));
        float so = 1.0f / (1.0f + expf(-go));
        c = sf * c + si * tanhf(gg);
        float h = so * tanhf(c);
        int j = s * 4 + rg;
        g_h[dir][idx & 1][j * 32 + b] = h;                    // full-precision h
        xout[((size_t)t * 32 + b) * 512 + dir * 256 + j] = h; // full-precision h
        __threadfence();
        __syncthreads();
        if (tid == 0) red_rel_add(&g_bar[dir], 1u);
    }
}

// ------------------------- LayerNorm + classifier (TF32 inputs to matmul) ---
__global__ __launch_bounds__(128) void ln_cls_k(const float* __restrict__ gamma,
                                                const float* __restrict__ beta,
                                                const float* __restrict__ cw,
                                                const float* __restrict__ cb,
                                                float* __restrict__ out) {
    int m = blockIdx.x;               // t*32+b
    int tid = threadIdx.x;
    __shared__ float xs[512];
    __shared__ float rs[8];
    __shared__ float red[9 * 4];
    float4 v = __ldg((const float4*)(g_x2 + (size_t)m * 512) + tid);
    *(float4*)&xs[tid * 4] = v;
    float s = v.x + v.y + v.z + v.w;
    float q = v.x * v.x + v.y * v.y + v.z * v.z + v.w * v.w;
#pragma unroll
    for (int o = 16; o; o >>= 1) {
        s += __shfl_down_sync(0xffffffffu, s, o);
        q += __shfl_down_sync(0xffffffffu, q, o);
    }
    int wid = tid >> 5, lane = tid & 31;
    if (lane == 0) { rs[wid] = s; rs[4 + wid] = q; }
    __syncthreads();
    float S = rs[0] + rs[1] + rs[2] + rs[3];
    float Q = rs[4] + rs[5] + rs[6] + rs[7];
    float mu = S * (1.0f / 512.0f);
    float var = Q * (1.0f / 512.0f) - mu * mu;
    float rstd = rsqrtf(var + 1e-5f);

    int d0 = tid * 4;
    float y0 = (xs[d0 + 0] - mu) * rstd * __ldg(gamma + d0 + 0) + __ldg(beta + d0 + 0);
    float y1 = (xs[d0 + 1] - mu) * rstd * __ldg(gamma + d0 + 1) + __ldg(beta + d0 + 1);
    float y2 = (xs[d0 + 2] - mu) * rstd * __ldg(gamma + d0 + 2) + __ldg(beta + d0 + 2);
    float y3 = (xs[d0 + 3] - mu) * rstd * __ldg(gamma + d0 + 3) + __ldg(beta + d0 + 3);
    float t0 = tf32r(y0), t1 = tf32r(y1), t2 = tf32r(y2), t3 = tf32r(y3);
    float acc[9];
#pragma unroll
    for (int l = 0; l < 9; ++l) {
        const float* w = cw + l * 512 + d0;
        acc[l] = t0 * tf32r(__ldg(w))     + t1 * tf32r(__ldg(w + 1))
               + t2 * tf32r(__ldg(w + 2)) + t3 * tf32r(__ldg(w + 3));
    }
#pragma unroll
    for (int l = 0; l < 9; ++l)
#pragma unroll
        for (int o = 16; o; o >>= 1) acc[l] += __shfl_down_sync(0xffffffffu, acc[l], o);
    if (lane == 0)
#pragma unroll
        for (int l = 0; l < 9; ++l) red[l * 4 + wid] = acc[l];
    __syncthreads();
    if (tid < 9) {
        float r = red[tid * 4] + red[tid * 4 + 1] + red[tid * 4 + 2] + red[tid * 4 + 3]
                + __ldg(cb + tid);
        int b = m & 31, t = m >> 5;
        out[1 + ((size_t)b * 512 + t) * 9 + tid] = r;  // logits (B,S,L)
    }
}

// ------------------------- CRF NLL, one warp per batch -------------------------
__global__ __launch_bounds__(32) void crf_k(const float* __restrict__ out,
                                            const int* __restrict__ labels,
                                            const int* __restrict__ lens,
                                            const float* __restrict__ trans) {
    __shared__ float T[121];          // (L+2)x(L+2) = 11x11
    int b = blockIdx.x;
    int lane = threadIdx.x;
    for (int i = lane; i < 121; i += 32) T[i] = trans[i];
    __syncwarp();
    int len = lens[b];
    const float* lg = out + 1 + (size_t)b * 512 * 9;
    const int* lab = labels + b * 512;

    // forward recursion
    float alpha = (lane < 9) ? T[9 * 11 + lane] + lg[lane] : -1e30f;
    for (int t = 1; t < len; ++t) {
        float e = (lane < 9) ? lg[t * 9 + lane] : 0.0f;
        float vv[9];
        float vmax = -1e30f;
#pragma unroll
        for (int i = 0; i < 9; ++i) {
            float ai = __shfl_sync(0xffffffffu, alpha, i);
            float v = ai + T[i * 11 + (lane < 9 ? lane : 0)];
            vv[i] = v;
            vmax = fmaxf(vmax, v);
        }
        float ssum = 0.0f;
#pragma unroll
        for (int i = 0; i < 9; ++i) ssum += expf(vv[i] - vmax);
        alpha = vmax + logf(ssum) + e;
    }
    // logZ
    float x = (lane < 9) ? alpha + T[lane * 11 + 10] : -1e30f;
    float mx = x;
#pragma unroll
    for (int o = 16; o; o >>= 1) mx = fmaxf(mx, __shfl_xor_sync(0xffffffffu, mx, o));
    float sm = expf(x - mx);
#pragma unroll
    for (int o = 16; o; o >>= 1) sm += __shfl_xor_sync(0xffffffffu, sm, o);
    float logZ = mx + logf(sm);

    // gold score
    float g = 0.0f;
    for (int t = lane; t < len; t += 32) {
        int y = lab[t];
        g += lg[t * 9 + y];
        if (t >= 1) g += T[lab[t - 1] * 11 + y];
    }
#pragma unroll
    for (int o = 16; o; o >>= 1) g += __shfl_xor_sync(0xffffffffu, g, o);
    if (lane == 0) {
        float gold = g + T[9 * 11 + lab[0]] + T[lab[len - 1] * 11 + 10];
        g_crf[b] = logZ - gold;
    }
}

__global__ __launch_bounds__(32) void loss_k(float* __restrict__ out) {
    float v = g_crf[threadIdx.x];
#pragma unroll
    for (int o = 16; o; o >>= 1) v += __shfl_xor_sync(0xffffffffu, v, o);
    if (threadIdx.x == 0) out[0] = v * (1.0f / 32.0f);
}

// ------------------------- launch -------------------------
extern "C" void kernel_launch(void* const* d_in, const int* in_sizes, int n_in,
                              void* d_out, int out_size) {
    const int* ids = (const int*)d_in[0];
    const int* msk = (const int*)d_in[1];
    const int* lens = (const int*)d_in[2];
    const int* labels = (const int*)d_in[3];
    const float* emb = (const float*)d_in[4];
    const float* wih = (const float*)d_in[5];
    const float* whh = (const float*)d_in[6];
    const float* bih = (const float*)d_in[7];
    const float* bhh = (const float*)d_in[8];
    const float* gamma = (const float*)d_in[9];
    const float* beta = (const float*)d_in[10];
    const float* cw = (const float*)d_in[11];
    const float* cb = (const float*)d_in[12];
    const float* trans = (const float*)d_in[13];
    float* out = (float*)d_out;

    embed_k<<<8192, 256>>>(ids, msk, emb);
    for (int l = 0; l < 2; ++l) {
        reset_k<<<128, 256>>>();
        gemm_pre<<<dim3(128, 8, 2), 256>>>(wih, bih, bhh, l);
        lstm_k<<<128, 128>>>(whh, l);
    }
    ln_cls_k<<<16384, 128>>>(gamma, beta, cw, cb, out);
    crf_k<<<32, 32>>>(out, labels, lens, trans);
    loss_k<<<1, 32>>>(out);
}

// round 14
// speedup vs baseline: 1.5784x; 1.3453x over previous
#include <cuda_runtime.h>
#include <cuda_bf16.h>
#include <math.h>

// Problem constants: B=32, S=512, V=32000, D=512, H=256, L=9, 4H=1024, 2H=512

// ------------------------- static device scratch -------------------------
__device__ float g_x0[512 * 32 * 512];        // embeddings  [t][b][d]
__device__ float g_x1[512 * 32 * 512];        // layer-0 out [t][b][2H]
__device__ float g_x2[512 * 32 * 512];        // layer-1 out [t][b][2H]
__device__ float g_preF[512 * 32 * 1024];     // x@Wih^T + biases, fwd
__device__ float g_preB[512 * 32 * 1024];     // bwd
__device__ float g_h[2][2][256 * 32];         // [dir][parity][j*32+b], tf32-rounded
__device__ unsigned g_bar[2];                 // per-direction step barrier
__device__ float g_crf[32];                   // per-batch (logZ - gold)

__device__ __forceinline__ float tf32r(float x) {
    float y;
    asm("cvt.rna.tf32.f32 %0, %1;" : "=f"(y) : "f"(x));
    return y;
}

__device__ __forceinline__ unsigned ld_acq_u32(const unsigned* p) {
    unsigned v;
    asm volatile("ld.acquire.gpu.global.u32 %0, [%1];" : "=r"(v) : "l"(p));
    return v;
}
__device__ __forceinline__ void red_rel_add(unsigned* p, unsigned v) {
    asm volatile("red.release.gpu.global.add.u32 [%0], %1;" :: "l"(p), "r"(v) : "memory");
}

// ------------------------- embedding gather -------------------------
__global__ __launch_bounds__(256) void embed_k(const int* __restrict__ ids,
                                               const int* __restrict__ msk,
                                               const float* __restrict__ emb) {
    int f = blockIdx.x * 256 + threadIdx.x;   // float4 index, 2,097,152 total
    int m = f >> 7;                            // row = t*32+b (128 float4/row)
    int d4 = f & 127;
    int b = m & 31, t = m >> 5;
    float mm = (float)msk[b * 512 + t];
    int id = ids[b * 512 + t];
    float4 v = __ldg((const float4*)emb + (size_t)id * 128 + d4);
    v.x *= mm; v.y *= mm; v.z *= mm; v.w *= mm;
    ((float4*)g_x0)[f] = v;
}

// ------------------------- reset barrier + h buffers -------------------------
__global__ void reset_k() {
    int i = blockIdx.x * blockDim.x + threadIdx.x;
    if (i < 2 * 2 * 256 * 32) ((float*)g_h)[i] = 0.0f;
    if (i < 2) g_bar[i] = 0u;
}

// ------------------------- pre-activation GEMM via tf32 mma.sync ----------
// C[m][n] = sum_k tf32(A[m][k]) * tf32(W[n][k]) + bih[n] + bhh[n]
// M=16384, N=1024(per dir), K=512.  BM=BN=128, BK=32, 256 threads.
__global__ __launch_bounds__(256, 1) void gemm_pre(const float* __restrict__ wih,
                                                   const float* __restrict__ bih,
                                                   const float* __restrict__ bhh,
                                                   int layer) {
    __shared__ float As[128 * 36];   // [m][k], pad 36 -> fragment LDS conflict-free
    __shared__ float Bs[128 * 36];   // [n][k]
    const float* A = layer ? g_x1 : g_x0;
    int dir = blockIdx.z;
    const float* Wp = wih + (size_t)(layer * 2 + dir) * 1024 * 512;
    const float* bi = bih + (layer * 2 + dir) * 1024;
    const float* bh = bhh + (layer * 2 + dir) * 1024;
    float* C = dir ? g_preB : g_preF;
    int m0 = blockIdx.x * 128, n0 = blockIdx.y * 128;
    int tid = threadIdx.x;
    int wid = tid >> 5, lane = tid & 31;
    int wm = wid & 3, wn = wid >> 2;       // 4x2 warp grid
    int gid = lane >> 2, tg = lane & 3;

    float acc[2][8][4];
#pragma unroll
    for (int mt = 0; mt < 2; ++mt)
#pragma unroll
        for (int nt = 0; nt < 8; ++nt)
#pragma unroll
            for (int i = 0; i < 4; ++i) acc[mt][nt][i] = 0.0f;

    float4 pa[4], pb[4];
#pragma unroll
    for (int i = 0; i < 4; ++i) {       // prefetch k-tile 0
        int f = i * 256 + tid;
        int m = f >> 3, kq = f & 7;
        pa[i] = __ldg((const float4*)(A + (size_t)(m0 + m) * 512 + kq * 4));
        pb[i] = __ldg((const float4*)(Wp + (size_t)(n0 + m) * 512 + kq * 4));
    }

    for (int kt = 0; kt < 16; ++kt) {
        __syncthreads();   // previous compute done before overwriting tiles
#pragma unroll
        for (int i = 0; i < 4; ++i) {
            int f = i * 256 + tid;
            int m = f >> 3, kq = f & 7;
            float4 a = pa[i], b = pb[i];
            a.x = tf32r(a.x); a.y = tf32r(a.y); a.z = tf32r(a.z); a.w = tf32r(a.w);
            b.x = tf32r(b.x); b.y = tf32r(b.y); b.z = tf32r(b.z); b.w = tf32r(b.w);
            *(float4*)&As[m * 36 + kq * 4] = a;
            *(float4*)&Bs[m * 36 + kq * 4] = b;
        }
        __syncthreads();
        if (kt < 15) {
            int k0 = (kt + 1) * 32;
#pragma unroll
            for (int i = 0; i < 4; ++i) {
                int f = i * 256 + tid;
                int m = f >> 3, kq = f & 7;
                pa[i] = __ldg((const float4*)(A + (size_t)(m0 + m) * 512 + k0 + kq * 4));
                pb[i] = __ldg((const float4*)(Wp + (size_t)(n0 + m) * 512 + k0 + kq * 4));
            }
        }
#pragma unroll
        for (int kk = 0; kk < 4; ++kk) {
            int kc = kk * 8;
            unsigned af[2][4];
#pragma unroll
            for (int mt = 0; mt < 2; ++mt) {
                int r = wm * 32 + mt * 16 + gid;
                af[mt][0] = __float_as_uint(As[r * 36 + kc + tg]);
                af[mt][1] = __float_as_uint(As[(r + 8) * 36 + kc + tg]);
                af[mt][2] = __float_as_uint(As[r * 36 + kc + tg + 4]);
                af[mt][3] = __float_as_uint(As[(r + 8) * 36 + kc + tg + 4]);
            }
#pragma unroll
            for (int nt = 0; nt < 8; ++nt) {
                int n = wn * 64 + nt * 8 + gid;
                unsigned b0 = __float_as_uint(Bs[n * 36 + kc + tg]);
                unsigned b1 = __float_as_uint(Bs[n * 36 + kc + tg + 4]);
#pragma unroll
                for (int mt = 0; mt < 2; ++mt) {
                    asm volatile(
                        "mma.sync.aligned.m16n8k8.row.col.f32.tf32.tf32.f32 "
                        "{%0,%1,%2,%3}, {%4,%5,%6,%7}, {%8,%9}, {%0,%1,%2,%3};"
                        : "+f"(acc[mt][nt][0]), "+f"(acc[mt][nt][1]),
                          "+f"(acc[mt][nt][2]), "+f"(acc[mt][nt][3])
                        : "r"(af[mt][0]), "r"(af[mt][1]), "r"(af[mt][2]), "r"(af[mt][3]),
                          "r"(b0), "r"(b1));
                }
            }
        }
    }
#pragma unroll
    for (int nt = 0; nt < 8; ++nt) {
        int colb = n0 + wn * 64 + nt * 8 + tg * 2;
        float bb0 = __ldg(bi + colb) + __ldg(bh + colb);
        float bb1 = __ldg(bi + colb + 1) + __ldg(bh + colb + 1);
#pragma unroll
        for (int mt = 0; mt < 2; ++mt) {
            int r0 = m0 + wm * 32 + mt * 16 + gid;
            float2 v0, v1;
            v0.x = acc[mt][nt][0] + bb0; v0.y = acc[mt][nt][1] + bb1;
            v1.x = acc[mt][nt][2] + bb0; v1.y = acc[mt][nt][3] + bb1;
            *(float2*)(C + (size_t)r0 * 1024 + colb) = v0;
            *(float2*)(C + (size_t)(r0 + 8) * 1024 + colb) = v1;
        }
    }
}

// ------------------------- persistent BiLSTM recurrence (tensor-core dot) ---
// 128 CTAs: CTAs 0..63 = fwd, 64..127 = bwd. Each CTA owns 4 hidden units
// (16 gate rows). Warp 0 holds the CTA's entire Whh slice as resident
// m16n8k8 TF32 A-fragments (loaded once; reused for all 512 steps) and does
// the h-dot with 128 mma.sync per step. All 128 threads (u=tid>>5, b=tid&31)
// then apply the gate nonlinearity for one (unit,batch) pair each.
// h layout in smem is XOR-swizzled so B-fragment LDS is bank-conflict-free:
//   word(k,b) = k*32 + (b ^ ((k&3)*8))
__global__ __launch_bounds__(128, 1) void lstm_k(const float* __restrict__ whh,
                                                 int layer) {
    __shared__ float hsm[8192];        // h_prev (tf32), swizzled [k][b]
    __shared__ float esm[16 * 34];     // gate dots exchange [row r][b], pad 34
    const int tid = threadIdx.x;
    const int cta = blockIdx.x;
    const int dir = cta >> 6;
    const int s = cta & 63;            // units s*4 .. s*4+3
    const int wid = tid >> 5;
    const int lane = tid & 31;
    const int u = wid;                 // unit owned for activation
    const int b = lane;                // batch owned for activation
    const int gid = lane >> 2, tg = lane & 3;
    const float* W = whh + (size_t)(layer * 2 + dir) * 1024 * 256;
    const float* pre = dir ? g_preB : g_preF;
    float* xout = layer ? g_x2 : g_x1;

    // warp 0: load resident A-fragments (Whh slice, tf32). rows r = g*4+ul,
    // global row = (r>>2)*256 + s*4 + (r&3). Frag rows: gid and gid+8.
    float areg[32][4];
    if (wid == 0) {
        int r0 = gid, r1 = gid + 8;
        const float* w0 = W + (size_t)((r0 >> 2) * 256 + s * 4 + (r0 & 3)) * 256;
        const float* w1 = W + (size_t)((r1 >> 2) * 256 + s * 4 + (r1 & 3)) * 256;
#pragma unroll
        for (int kt = 0; kt < 32; ++kt) {
            areg[kt][0] = tf32r(__ldg(w0 + kt * 8 + tg));
            areg[kt][1] = tf32r(__ldg(w1 + kt * 8 + tg));
            areg[kt][2] = tf32r(__ldg(w0 + kt * 8 + tg + 4));
            areg[kt][3] = tf32r(__ldg(w1 + kt * 8 + tg + 4));
        }
    }
    float c = 0.0f;
    __syncthreads();

    for (int idx = 0; idx < 512; ++idx) {
        const int t = dir ? (511 - idx) : idx;
        if (tid == 0 && idx > 0) {
            unsigned tgt = 64u * (unsigned)idx;
            while (ld_acq_u32(&g_bar[dir]) < tgt) { }
        }
        __syncthreads();   // barrier observed by all; also guards hsm overwrite

        // copy previous h (already tf32 at producer) into swizzled smem
        {
            const float4* src = (const float4*)g_h[dir][(idx + 1) & 1];
#pragma unroll
            for (int i = 0; i < 16; ++i) {
                int f = i * 128 + tid;         // 0..2047 float4
                int k = f >> 3, b4 = f & 7;
                float4 hv = __ldcg(src + f);
                *(float4*)&hsm[k * 32 + ((b4 * 4) ^ ((k & 3) * 8))] = hv;
            }
        }
        // fetch pre-activations for this thread's (unit, batch): 4 gates
        const float* pb = pre + ((size_t)t * 32 + b) * 1024 + s * 4 + u;
        float pv0 = __ldg(pb);
        float pv1 = __ldg(pb + 256);
        float pv2 = __ldg(pb + 512);
        float pv3 = __ldg(pb + 768);
        __syncthreads();

        if (wid == 0) {
            float acc[4][4];
#pragma unroll
            for (int nt = 0; nt < 4; ++nt)
#pragma unroll
                for (int i = 0; i < 4; ++i) acc[nt][i] = 0.0f;
#pragma unroll
            for (int kt = 0; kt < 32; ++kt) {
                int kc = kt * 8;
#pragma unroll
                for (int nt = 0; nt < 4; ++nt) {
                    unsigned b0 = __float_as_uint(
                        hsm[(kc + tg) * 32 + ((nt * 8 + gid) ^ (tg * 8))]);
                    unsigned b1 = __float_as_uint(
                        hsm[(kc + tg + 4) * 32 + ((nt * 8 + gid) ^ (tg * 8))]);
                    asm volatile(
                        "mma.sync.aligned.m16n8k8.row.col.f32.tf32.tf32.f32 "
                        "{%0,%1,%2,%3}, {%4,%5,%6,%7}, {%8,%9}, {%0,%1,%2,%3};"
                        : "+f"(acc[nt][0]), "+f"(acc[nt][1]),
                          "+f"(acc[nt][2]), "+f"(acc[nt][3])
                        : "r"(__float_as_uint(areg[kt][0])),
                          "r"(__float_as_uint(areg[kt][1])),
                          "r"(__float_as_uint(areg[kt][2])),
                          "r"(__float_as_uint(areg[kt][3])),
                          "r"(b0), "r"(b1));
                }
            }
            // write gate dots to exchange smem: rows gid / gid+8, cols nt*8+2tg
#pragma unroll
            for (int nt = 0; nt < 4; ++nt) {
                int col = nt * 8 + tg * 2;
                float2 v0 = make_float2(acc[nt][0], acc[nt][1]);
                float2 v1 = make_float2(acc[nt][2], acc[nt][3]);
                *(float2*)&esm[gid * 34 + col] = v0;
                *(float2*)&esm[(gid + 8) * 34 + col] = v1;
            }
        }
        __syncthreads();

        // activation: thread (u,b). gate g dot at esm[(g*4+u)*34 + b]
        float gi = esm[(0 * 4 + u) * 34 + b] + pv0;
        float gf = esm[(1 * 4 + u) * 34 + b] + pv1;
        float gg = esm[(2 * 4 + u) * 34 + b] + pv2;
        float go = esm[(3 * 4 + u) * 34 + b] + pv3;
        float si = __fdividef(1.0f, 1.0f + __expf(-gi));
        float sf = __fdividef(1.0f, 1.0f + __expf(-gf));
        float so = __fdividef(1.0f, 1.0f + __expf(-go));
        float tg_ = __fdividef(2.0f, 1.0f + __expf(-2.0f * gg)) - 1.0f;
        c = sf * c + si * tg_;
        float th = __fdividef(2.0f, 1.0f + __expf(-2.0f * c)) - 1.0f;
        float h = so * th;
        int j = s * 4 + u;
        g_h[dir][idx & 1][j * 32 + b] = tf32r(h);             // tf32 for next dot
        xout[((size_t)t * 32 + b) * 512 + dir * 256 + j] = h; // full precision
        __syncthreads();
        if (tid == 0) red_rel_add(&g_bar[dir], 1u);
    }
}

// ------------------------- LayerNorm + classifier (TF32 inputs to matmul) ---
__global__ __launch_bounds__(128) void ln_cls_k(const float* __restrict__ gamma,
                                                const float* __restrict__ beta,
                                                const float* __restrict__ cw,
                                                const float* __restrict__ cb,
                                                float* __restrict__ out) {
    int m = blockIdx.x;               // t*32+b
    int tid = threadIdx.x;
    __shared__ float xs[512];
    __shared__ float rs[8];
    __shared__ float red[9 * 4];
    float4 v = __ldg((const float4*)(g_x2 + (size_t)m * 512) + tid);
    *(float4*)&xs[tid * 4] = v;
    float s = v.x + v.y + v.z + v.w;
    float q = v.x * v.x + v.y * v.y + v.z * v.z + v.w * v.w;
#pragma unroll
    for (int o = 16; o; o >>= 1) {
        s += __shfl_down_sync(0xffffffffu, s, o);
        q += __shfl_down_sync(0xffffffffu, q, o);
    }
    int wid = tid >> 5, lane = tid & 31;
    if (lane == 0) { rs[wid] = s; rs[4 + wid] = q; }
    __syncthreads();
    float S = rs[0] + rs[1] + rs[2] + rs[3];
    float Q = rs[4] + rs[5] + rs[6] + rs[7];
    float mu = S * (1.0f / 512.0f);
    float var = Q * (1.0f / 512.0f) - mu * mu;
    float rstd = rsqrtf(var + 1e-5f);

    int d0 = tid * 4;
    float y0 = (xs[d0 + 0] - mu) * rstd * __ldg(gamma + d0 + 0) + __ldg(beta + d0 + 0);
    float y1 = (xs[d0 + 1] - mu) * rstd * __ldg(gamma + d0 + 1) + __ldg(beta + d0 + 1);
    float y2 = (xs[d0 + 2] - mu) * rstd * __ldg(gamma + d0 + 2) + __ldg(beta + d0 + 2);
    float y3 = (xs[d0 + 3] - mu) * rstd * __ldg(gamma + d0 + 3) + __ldg(beta + d0 + 3);
    float t0 = tf32r(y0), t1 = tf32r(y1), t2 = tf32r(y2), t3 = tf32r(y3);
    float acc[9];
#pragma unroll
    for (int l = 0; l < 9; ++l) {
        const float* w = cw + l * 512 + d0;
        acc[l] = t0 * tf32r(__ldg(w))     + t1 * tf32r(__ldg(w + 1))
               + t2 * tf32r(__ldg(w + 2)) + t3 * tf32r(__ldg(w + 3));
    }
#pragma unroll
    for (int l = 0; l < 9; ++l)
#pragma unroll
        for (int o = 16; o; o >>= 1) acc[l] += __shfl_down_sync(0xffffffffu, acc[l], o);
    if (lane == 0)
#pragma unroll
        for (int l = 0; l < 9; ++l) red[l * 4 + wid] = acc[l];
    __syncthreads();
    if (tid < 9) {
        float r = red[tid * 4] + red[tid * 4 + 1] + red[tid * 4 + 2] + red[tid * 4 + 3]
                + __ldg(cb + tid);
        int b = m & 31, t = m >> 5;
        out[1 + ((size_t)b * 512 + t) * 9 + tid] = r;  // logits (B,S,L)
    }
}

// ------------------------- CRF NLL, one warp per batch -------------------------
__global__ __launch_bounds__(32) void crf_k(const float* __restrict__ out,
                                            const int* __restrict__ labels,
                                            const int* __restrict__ lens,
                                            const float* __restrict__ trans) {
    __shared__ float T[121];          // (L+2)x(L+2) = 11x11
    int b = blockIdx.x;
    int lane = threadIdx.x;
    for (int i = lane; i < 121; i += 32) T[i] = trans[i];
    __syncwarp();
    int len = lens[b];
    const float* lg = out + 1 + (size_t)b * 512 * 9;
    const int* lab = labels + b * 512;

    float alpha = (lane < 9) ? T[9 * 11 + lane] + lg[lane] : -1e30f;
    for (int t = 1; t < len; ++t) {
        float e = (lane < 9) ? lg[t * 9 + lane] : 0.0f;
        float vv[9];
        float vmax = -1e30f;
#pragma unroll
        for (int i = 0; i < 9; ++i) {
            float ai = __shfl_sync(0xffffffffu, alpha, i);
            float v = ai + T[i * 11 + (lane < 9 ? lane : 0)];
            vv[i] = v;
            vmax = fmaxf(vmax, v);
        }
        float ssum = 0.0f;
#pragma unroll
        for (int i = 0; i < 9; ++i) ssum += expf(vv[i] - vmax);
        alpha = vmax + logf(ssum) + e;
    }
    float x = (lane < 9) ? alpha + T[lane * 11 + 10] : -1e30f;
    float mx = x;
#pragma unroll
    for (int o = 16; o; o >>= 1) mx = fmaxf(mx, __shfl_xor_sync(0xffffffffu, mx, o));
    float sm = expf(x - mx);
#pragma unroll
    for (int o = 16; o; o >>= 1) sm += __shfl_xor_sync(0xffffffffu, sm, o);
    float logZ = mx + logf(sm);

    float g = 0.0f;
    for (int t = lane; t < len; t += 32) {
        int y = lab[t];
        g += lg[t * 9 + y];
        if (t >= 1) g += T[lab[t - 1] * 11 + y];
    }
#pragma unroll
    for (int o = 16; o; o >>= 1) g += __shfl_xor_sync(0xffffffffu, g, o);
    if (lane == 0) {
        float gold = g + T[9 * 11 + lab[0]] + T[lab[len - 1] * 11 + 10];
        g_crf[b] = logZ - gold;
    }
}

__global__ __launch_bounds__(32) void loss_k(float* __restrict__ out) {
    float v = g_crf[threadIdx.x];
#pragma unroll
    for (int o = 16; o; o >>= 1) v += __shfl_xor_sync(0xffffffffu, v, o);
    if (threadIdx.x == 0) out[0] = v * (1.0f / 32.0f);
}

// ------------------------- launch -------------------------
extern "C" void kernel_launch(void* const* d_in, const int* in_sizes, int n_in,
                              void* d_out, int out_size) {
    const int* ids = (const int*)d_in[0];
    const int* msk = (const int*)d_in[1];
    const int* lens = (const int*)d_in[2];
    const int* labels = (const int*)d_in[3];
    const float* emb = (const float*)d_in[4];
    const float* wih = (const float*)d_in[5];
    const float* whh = (const float*)d_in[6];
    const float* bih = (const float*)d_in[7];
    const float* bhh = (const float*)d_in[8];
    const float* gamma = (const float*)d_in[9];
    const float* beta = (const float*)d_in[10];
    const float* cw = (const float*)d_in[11];
    const float* cb = (const float*)d_in[12];
    const float* trans = (const float*)d_in[13];
    float* out = (float*)d_out;

    embed_k<<<8192, 256>>>(ids, msk, emb);
    for (int l = 0; l < 2; ++l) {
        reset_k<<<128, 256>>>();
        gemm_pre<<<dim3(128, 8, 2), 256>>>(wih, bih, bhh, l);
        lstm_k<<<128, 128>>>(whh, l);
    }
    ln_cls_k<<<16384, 128>>>(gamma, beta, cw, cb, out);
    crf_k<<<32, 32>>>(out, labels, lens, trans);
    loss_k<<<1, 32>>>(out);
}

// round 17
// speedup vs baseline: 1.6947x; 1.0737x over previous
#include <cuda_runtime.h>
#include <cuda_bf16.h>
#include <math.h>

// Problem constants: B=32, S=512, V=32000, D=512, H=256, L=9, 4H=1024, 2H=512

// ------------------------- static device scratch -------------------------
__device__ float g_x0[512 * 32 * 512];        // embeddings  [t][b][d]
__device__ float g_x1[512 * 32 * 512];        // layer-0 out [t][b][2H]
__device__ float g_x2[512 * 32 * 512];        // layer-1 out [t][b][2H]
__device__ float g_preF[512 * 32 * 1024];     // x@Wih^T + biases, fwd
__device__ float g_preB[512 * 32 * 1024];     // bwd
__device__ float g_h[2][2][256 * 32];         // [dir][parity][j*32+b], tf32-rounded
__device__ unsigned g_bar[2];                 // per-direction step barrier
__device__ float g_crf[32];                   // per-batch (logZ - gold)

__device__ __forceinline__ float tf32r(float x) {
    float y;
    asm("cvt.rna.tf32.f32 %0, %1;" : "=f"(y) : "f"(x));
    return y;
}

__device__ __forceinline__ unsigned ld_acq_u32(const unsigned* p) {
    unsigned v;
    asm volatile("ld.acquire.gpu.global.u32 %0, [%1];" : "=r"(v) : "l"(p));
    return v;
}
__device__ __forceinline__ void red_rel_add(unsigned* p, unsigned v) {
    asm volatile("red.release.gpu.global.add.u32 [%0], %1;" :: "l"(p), "r"(v) : "memory");
}

// ------------------------- embedding gather -------------------------
__global__ __launch_bounds__(256) void embed_k(const int* __restrict__ ids,
                                               const int* __restrict__ msk,
                                               const float* __restrict__ emb) {
    int f = blockIdx.x * 256 + threadIdx.x;   // float4 index, 2,097,152 total
    int m = f >> 7;                            // row = t*32+b (128 float4/row)
    int d4 = f & 127;
    int b = m & 31, t = m >> 5;
    float mm = (float)msk[b * 512 + t];
    int id = ids[b * 512 + t];
    float4 v = __ldg((const float4*)emb + (size_t)id * 128 + d4);
    v.x *= mm; v.y *= mm; v.z *= mm; v.w *= mm;
    ((float4*)g_x0)[f] = v;
}

// ------------------------- reset barrier + h buffers -------------------------
__global__ void reset_k() {
    int i = blockIdx.x * blockDim.x + threadIdx.x;
    if (i < 2 * 2 * 256 * 32) ((float*)g_h)[i] = 0.0f;
    if (i < 2) g_bar[i] = 0u;
}

// ------------------------- pre-activation GEMM via tf32 mma.sync ----------
// C[m][n] = sum_k tf32(A[m][k]) * tf32(W[n][k]) + bih[n] + bhh[n]
// M=16384, N=1024(per dir), K=512.  BM=BN=128, BK=32, 256 threads.
__global__ __launch_bounds__(256, 1) void gemm_pre(const float* __restrict__ wih,
                                                   const float* __restrict__ bih,
                                                   const float* __restrict__ bhh,
                                                   int layer) {
    __shared__ float As[128 * 36];   // [m][k], pad 36 -> fragment LDS conflict-free
    __shared__ float Bs[128 * 36];   // [n][k]
    const float* A = layer ? g_x1 : g_x0;
    int dir = blockIdx.z;
    const float* Wp = wih + (size_t)(layer * 2 + dir) * 1024 * 512;
    const float* bi = bih + (layer * 2 + dir) * 1024;
    const float* bh = bhh + (layer * 2 + dir) * 1024;
    float* C = dir ? g_preB : g_preF;
    int m0 = blockIdx.x * 128, n0 = blockIdx.y * 128;
    int tid = threadIdx.x;
    int wid = tid >> 5, lane = tid & 31;
    int wm = wid & 3, wn = wid >> 2;       // 4x2 warp grid
    int gid = lane >> 2, tg = lane & 3;

    float acc[2][8][4];
#pragma unroll
    for (int mt = 0; mt < 2; ++mt)
#pragma unroll
        for (int nt = 0; nt < 8; ++nt)
#pragma unroll
            for (int i = 0; i < 4; ++i) acc[mt][nt][i] = 0.0f;

    float4 pa[4], pb[4];
#pragma unroll
    for (int i = 0; i < 4; ++i) {       // prefetch k-tile 0
        int f = i * 256 + tid;
        int m = f >> 3, kq = f & 7;
        pa[i] = __ldg((const float4*)(A + (size_t)(m0 + m) * 512 + kq * 4));
        pb[i] = __ldg((const float4*)(Wp + (size_t)(n0 + m) * 512 + kq * 4));
    }

    for (int kt = 0; kt < 16; ++kt) {
        __syncthreads();   // previous compute done before overwriting tiles
#pragma unroll
        for (int i = 0; i < 4; ++i) {
            int f = i * 256 + tid;
            int m = f >> 3, kq = f & 7;
            float4 a = pa[i], b = pb[i];
            a.x = tf32r(a.x); a.y = tf32r(a.y); a.z = tf32r(a.z); a.w = tf32r(a.w);
            b.x = tf32r(b.x); b.y = tf32r(b.y); b.z = tf32r(b.z); b.w = tf32r(b.w);
            *(float4*)&As[m * 36 + kq * 4] = a;
            *(float4*)&Bs[m * 36 + kq * 4] = b;
        }
        __syncthreads();
        if (kt < 15) {
            int k0 = (kt + 1) * 32;
#pragma unroll
            for (int i = 0; i < 4; ++i) {
                int f = i * 256 + tid;
                int m = f >> 3, kq = f & 7;
                pa[i] = __ldg((const float4*)(A + (size_t)(m0 + m) * 512 + k0 + kq * 4));
                pb[i] = __ldg((const float4*)(Wp + (size_t)(n0 + m) * 512 + k0 + kq * 4));
            }
        }
#pragma unroll
        for (int kk = 0; kk < 4; ++kk) {
            int kc = kk * 8;
            unsigned af[2][4];
#pragma unroll
            for (int mt = 0; mt < 2; ++mt) {
                int r = wm * 32 + mt * 16 + gid;
                af[mt][0] = __float_as_uint(As[r * 36 + kc + tg]);
                af[mt][1] = __float_as_uint(As[(r + 8) * 36 + kc + tg]);
                af[mt][2] = __float_as_uint(As[r * 36 + kc + tg + 4]);
                af[mt][3] = __float_as_uint(As[(r + 8) * 36 + kc + tg + 4]);
            }
#pragma unroll
            for (int nt = 0; nt < 8; ++nt) {
                int n = wn * 64 + nt * 8 + gid;
                unsigned b0 = __float_as_uint(Bs[n * 36 + kc + tg]);
                unsigned b1 = __float_as_uint(Bs[n * 36 + kc + tg + 4]);
#pragma unroll
                for (int mt = 0; mt < 2; ++mt) {
                    asm volatile(
                        "mma.sync.aligned.m16n8k8.row.col.f32.tf32.tf32.f32 "
                        "{%0,%1,%2,%3}, {%4,%5,%6,%7}, {%8,%9}, {%0,%1,%2,%3};"
                        : "+f"(acc[mt][nt][0]), "+f"(acc[mt][nt][1]),
                          "+f"(acc[mt][nt][2]), "+f"(acc[mt][nt][3])
                        : "r"(af[mt][0]), "r"(af[mt][1]), "r"(af[mt][2]), "r"(af[mt][3]),
                          "r"(b0), "r"(b1));
                }
            }
        }
    }
#pragma unroll
    for (int nt = 0; nt < 8; ++nt) {
        int colb = n0 + wn * 64 + nt * 8 + tg * 2;
        float bb0 = __ldg(bi + colb) + __ldg(bh + colb);
        float bb1 = __ldg(bi + colb + 1) + __ldg(bh + colb + 1);
#pragma unroll
        for (int mt = 0; mt < 2; ++mt) {
            int r0 = m0 + wm * 32 + mt * 16 + gid;
            float2 v0, v1;
            v0.x = acc[mt][nt][0] + bb0; v0.y = acc[mt][nt][1] + bb1;
            v1.x = acc[mt][nt][2] + bb0; v1.y = acc[mt][nt][3] + bb1;
            *(float2*)(C + (size_t)r0 * 1024 + colb) = v0;
            *(float2*)(C + (size_t)(r0 + 8) * 1024 + colb) = v1;
        }
    }
}

// ------------------------- persistent BiLSTM recurrence (tensor-core dot) ---
// 128 CTAs: CTAs 0..63 = fwd, 64..127 = bwd. Each CTA owns 4 hidden units
// (16 gate rows r = gate*4+unit). The h-dot (16x32, K=256) is K-SPLIT across
// all 4 warps: warp w owns k in [64w, 64w+64), holding its Whh slice as 32
// resident TF32 A-fragment registers, and loads B-fragments (h) directly
// from global with __ldcg (fragment pattern touches each 32B sector once).
// Partials are reduced through smem (scalar stores — pad-33 rows are NOT
// 8B-aligned, float2 stores trap); each thread (u=tid>>5, b=tid&31) then
// applies the gate nonlinearity for one (unit,batch) pair.
__global__ __launch_bounds__(128, 1) void lstm_k(const float* __restrict__ whh,
                                                 int layer) {
    __shared__ float esm[4 * 16 * 33];  // [w][r][b] partial dots, pad 33
    const int tid = threadIdx.x;
    const int cta = blockIdx.x;
    const int dir = cta >> 6;
    const int s = cta & 63;            // units s*4 .. s*4+3
    const int wid = tid >> 5;
    const int lane = tid & 31;
    const int u = wid;                 // unit owned for activation
    const int b = lane;                // batch owned for activation
    const int gid = lane >> 2, tg = lane & 3;
    const float* W = whh + (size_t)(layer * 2 + dir) * 1024 * 256;
    const float* pre = dir ? g_preB : g_preF;
    float* xout = layer ? g_x2 : g_x1;

    // resident A-fragments: rows gid / gid+8, this warp's k-slice
    float areg[8][4];
    {
        int r0 = gid, r1 = gid + 8;
        const float* w0 = W + (size_t)((r0 >> 2) * 256 + s * 4 + (r0 & 3)) * 256 + wid * 64;
        const float* w1 = W + (size_t)((r1 >> 2) * 256 + s * 4 + (r1 & 3)) * 256 + wid * 64;
#pragma unroll
        for (int kt = 0; kt < 8; ++kt) {
            areg[kt][0] = tf32r(__ldg(w0 + kt * 8 + tg));
            areg[kt][1] = tf32r(__ldg(w1 + kt * 8 + tg));
            areg[kt][2] = tf32r(__ldg(w0 + kt * 8 + tg + 4));
            areg[kt][3] = tf32r(__ldg(w1 + kt * 8 + tg + 4));
        }
    }
    float c = 0.0f;

    for (int idx = 0; idx < 512; ++idx) {
        const int t = dir ? (511 - idx) : idx;
        if (idx > 0) {                     // all threads spin (L2 broadcast)
            unsigned tgt = 64u * (unsigned)idx;
            while (ld_acq_u32(&g_bar[dir]) < tgt) { }
        }
        const float* hb = g_h[dir][(idx + 1) & 1];   // [k*32 + b]

        // fragment dot: 32 mma per warp, B-frags straight from L2
        float acc[4][4];
#pragma unroll
        for (int nt = 0; nt < 4; ++nt)
#pragma unroll
            for (int i = 0; i < 4; ++i) acc[nt][i] = 0.0f;
#pragma unroll
        for (int kt = 0; kt < 8; ++kt) {
            int kc = wid * 64 + kt * 8;
            float bf[4][2];
#pragma unroll
            for (int nt = 0; nt < 4; ++nt) {
                bf[nt][0] = __ldcg(hb + (kc + tg) * 32 + nt * 8 + gid);
                bf[nt][1] = __ldcg(hb + (kc + tg + 4) * 32 + nt * 8 + gid);
            }
#pragma unroll
            for (int nt = 0; nt < 4; ++nt) {
                asm volatile(
                    "mma.sync.aligned.m16n8k8.row.col.f32.tf32.tf32.f32 "
                    "{%0,%1,%2,%3}, {%4,%5,%6,%7}, {%8,%9}, {%0,%1,%2,%3};"
                    : "+f"(acc[nt][0]), "+f"(acc[nt][1]),
                      "+f"(acc[nt][2]), "+f"(acc[nt][3])
                    : "r"(__float_as_uint(areg[kt][0])),
                      "r"(__float_as_uint(areg[kt][1])),
                      "r"(__float_as_uint(areg[kt][2])),
                      "r"(__float_as_uint(areg[kt][3])),
                      "r"(__float_as_uint(bf[nt][0])),
                      "r"(__float_as_uint(bf[nt][1])));
            }
        }
        // pre-activations for (u, b): 4 gates
        const float* pb = pre + ((size_t)t * 32 + b) * 1024 + s * 4 + u;
        float pv0 = __ldg(pb);
        float pv1 = __ldg(pb + 256);
        float pv2 = __ldg(pb + 512);
        float pv3 = __ldg(pb + 768);

        // write partials (scalar STS): rows gid / gid+8, cols nt*8 + tg*2
        float* ep = esm + wid * 528;
#pragma unroll
        for (int nt = 0; nt < 4; ++nt) {
            int col = nt * 8 + tg * 2;
            ep[gid * 33 + col]           = acc[nt][0];
            ep[gid * 33 + col + 1]       = acc[nt][1];
            ep[(gid + 8) * 33 + col]     = acc[nt][2];
            ep[(gid + 8) * 33 + col + 1] = acc[nt][3];
        }
        __syncthreads();

        // reduce 4 partials + activation; row r = gate*4 + u
        float gi = pv0, gf = pv1, gg = pv2, go = pv3;
#pragma unroll
        for (int w = 0; w < 4; ++w) {
            const float* q = esm + w * 528;
            gi += q[(0 + u) * 33 + b];
            gf += q[(4 + u) * 33 + b];
            gg += q[(8 + u) * 33 + b];
            go += q[(12 + u) * 33 + b];
        }
        float si = __fdividef(1.0f, 1.0f + __expf(-gi));
        float sf = __fdividef(1.0f, 1.0f + __expf(-gf));
        float so = __fdividef(1.0f, 1.0f + __expf(-go));
        float tg_ = __fdividef(2.0f, 1.0f + __expf(-2.0f * gg)) - 1.0f;
        c = sf * c + si * tg_;
        float th = __fdividef(2.0f, 1.0f + __expf(-2.0f * c)) - 1.0f;
        float h = so * th;
        int j = s * 4 + u;
        g_h[dir][idx & 1][j * 32 + b] = tf32r(h);             // tf32 for next dot
        xout[((size_t)t * 32 + b) * 512 + dir * 256 + j] = h; // full precision
        __syncthreads();          // stores + esm reads done CTA-wide
        if (tid == 0) red_rel_add(&g_bar[dir], 1u);
    }
}

// ------------------------- LayerNorm + classifier (TF32 inputs to matmul) ---
__global__ __launch_bounds__(128) void ln_cls_k(const float* __restrict__ gamma,
                                                const float* __restrict__ beta,
                                                const float* __restrict__ cw,
                                                const float* __restrict__ cb,
                                                float* __restrict__ out) {
    int m = blockIdx.x;               // t*32+b
    int tid = threadIdx.x;
    __shared__ float xs[512];
    __shared__ float rs[8];
    __shared__ float red[9 * 4];
    float4 v = __ldg((const float4*)(g_x2 + (size_t)m * 512) + tid);
    *(float4*)&xs[tid * 4] = v;
    float s = v.x + v.y + v.z + v.w;
    float q = v.x * v.x + v.y * v.y + v.z * v.z + v.w * v.w;
#pragma unroll
    for (int o = 16; o; o >>= 1) {
        s += __shfl_down_sync(0xffffffffu, s, o);
        q += __shfl_down_sync(0xffffffffu, q, o);
    }
    int wid = tid >> 5, lane = tid & 31;
    if (lane == 0) { rs[wid] = s; rs[4 + wid] = q; }
    __syncthreads();
    float S = rs[0] + rs[1] + rs[2] + rs[3];
    float Q = rs[4] + rs[5] + rs[6] + rs[7];
    float mu = S * (1.0f / 512.0f);
    float var = Q * (1.0f / 512.0f) - mu * mu;
    float rstd = rsqrtf(var + 1e-5f);

    int d0 = tid * 4;
    float y0 = (xs[d0 + 0] - mu) * rstd * __ldg(gamma + d0 + 0) + __ldg(beta + d0 + 0);
    float y1 = (xs[d0 + 1] - mu) * rstd * __ldg(gamma + d0 + 1) + __ldg(beta + d0 + 1);
    float y2 = (xs[d0 + 2] - mu) * rstd * __ldg(gamma + d0 + 2) + __ldg(beta + d0 + 2);
    float y3 = (xs[d0 + 3] - mu) * rstd * __ldg(gamma + d0 + 3) + __ldg(beta + d0 + 3);
    float t0 = tf32r(y0), t1 = tf32r(y1), t2 = tf32r(y2), t3 = tf32r(y3);
    float acc[9];
#pragma unroll
    for (int l = 0; l < 9; ++l) {
        const float* w = cw + l * 512 + d0;
        acc[l] = t0 * tf32r(__ldg(w))     + t1 * tf32r(__ldg(w + 1))
               + t2 * tf32r(__ldg(w + 2)) + t3 * tf32r(__ldg(w + 3));
    }
#pragma unroll
    for (int l = 0; l < 9; ++l)
#pragma unroll
        for (int o = 16; o; o >>= 1) acc[l] += __shfl_down_sync(0xffffffffu, acc[l], o);
    if (lane == 0)
#pragma unroll
        for (int l = 0; l < 9; ++l) red[l * 4 + wid] = acc[l];
    __syncthreads();
    if (tid < 9) {
        float r = red[tid * 4] + red[tid * 4 + 1] + red[tid * 4 + 2] + red[tid * 4 + 3]
                + __ldg(cb + tid);
        int b = m & 31, t = m >> 5;
        out[1 + ((size_t)b * 512 + t) * 9 + tid] = r;  // logits (B,S,L)
    }
}

// ------------------------- CRF NLL, one warp per batch -------------------------
__global__ __launch_bounds__(32) void crf_k(const float* __restrict__ out,
                                            const int* __restrict__ labels,
                                            const int* __restrict__ lens,
                                            const float* __restrict__ trans) {
    __shared__ float T[121];          // (L+2)x(L+2) = 11x11
    int b = blockIdx.x;
    int lane = threadIdx.x;
    for (int i = lane; i < 121; i += 32) T[i] = trans[i];
    __syncwarp();
    int len = lens[b];
    const float* lg = out + 1 + (size_t)b * 512 * 9;
    const int* lab = labels + b * 512;

    float alpha = (lane < 9) ? T[9 * 11 + lane] + lg[lane] : -1e30f;
    for (int t = 1; t < len; ++t) {
        float e = (lane < 9) ? lg[t * 9 + lane] : 0.0f;
        float vv[9];
        float vmax = -1e30f;
#pragma unroll
        for (int i = 0; i < 9; ++i) {
            float ai = __shfl_sync(0xffffffffu, alpha, i);
            float v = ai + T[i * 11 + (lane < 9 ? lane : 0)];
            vv[i] = v;
            vmax = fmaxf(vmax, v);
        }
        float ssum = 0.0f;
#pragma unroll
        for (int i = 0; i < 9; ++i) ssum += expf(vv[i] - vmax);
        alpha = vmax + logf(ssum) + e;
    }
    float x = (lane < 9) ? alpha + T[lane * 11 + 10] : -1e30f;
    float mx = x;
#pragma unroll
    for (int o = 16; o; o >>= 1) mx = fmaxf(mx, __shfl_xor_sync(0xffffffffu, mx, o));
    float sm = expf(x - mx);
#pragma unroll
    for (int o = 16; o; o >>= 1) sm += __shfl_xor_sync(0xffffffffu, sm, o);
    float logZ = mx + logf(sm);

    float g = 0.0f;
    for (int t = lane; t < len; t += 32) {
        int y = lab[t];
        g += lg[t * 9 + y];
        if (t >= 1) g += T[lab[t - 1] * 11 + y];
    }
#pragma unroll
    for (int o = 16; o; o >>= 1) g += __shfl_xor_sync(0xffffffffu, g, o);
    if (lane == 0) {
        float gold = g + T[9 * 11 + lab[0]] + T[lab[len - 1] * 11 + 10];
        g_crf[b] = logZ - gold;
    }
}

__global__ __launch_bounds__(32) void loss_k(float* __restrict__ out) {
    float v = g_crf[threadIdx.x];
#pragma unroll
    for (int o = 16; o; o >>= 1) v += __shfl_xor_sync(0xffffffffu, v, o);
    if (threadIdx.x == 0) out[0] = v * (1.0f / 32.0f);
}

// ------------------------- launch -------------------------
extern "C" void kernel_launch(void* const* d_in, const int* in_sizes, int n_in,
                              void* d_out, int out_size) {
    const int* ids = (const int*)d_in[0];
    const int* msk = (const int*)d_in[1];
    const int* lens = (const int*)d_in[2];
    const int* labels = (const int*)d_in[3];
    const float* emb = (const float*)d_in[4];
    const float* wih = (const float*)d_in[5];
    const float* whh = (const float*)d_in[6];
    const float* bih = (const float*)d_in[7];
    const float* bhh = (const float*)d_in[8];
    const float* gamma = (const float*)d_in[9];
    const float* beta = (const float*)d_in[10];
    const float* cw = (const float*)d_in[11];
    const float* cb = (const float*)d_in[12];
    const float* trans = (const float*)d_in[13];
    float* out = (float*)d_out;

    embed_k<<<8192, 256>>>(ids, msk, emb);
    for (int l = 0; l < 2; ++l) {
        reset_k<<<128, 256>>>();
        gemm_pre<<<dim3(128, 8, 2), 256>>>(wih, bih, bhh, l);
        lstm_k<<<128, 128>>>(whh, l);
    }
    ln_cls_k<<<16384, 128>>>(gamma, beta, cw, cb, out);
    crf_k<<<32, 32>>>(out, labels, lens, trans);
    loss_k<<<1, 32>>>(out);
}